// round 4
// baseline (speedup 1.0000x reference)
#include <cuda_runtime.h>
#include <cuda_bf16.h>
#include <cstdint>

// Problem constants
#define BLROWS 4096   // B*L = 2*2048
#define LSEQ   2048
#define DMODEL 1024
#define DINNER 2048
#define DSTATE 16
#define DTRANK 64

typedef __nv_bfloat16 bf16;

// ---------------------------------------------------------------------------
// Scratch (device globals)
// ---------------------------------------------------------------------------
__device__ bf16  g_xh [(size_t)BLROWS * DMODEL];    // x split
__device__ bf16  g_xl [(size_t)BLROWS * DMODEL];
__device__ bf16  g_xsh[(size_t)BLROWS * DINNER];    // xs (conv input) split
__device__ bf16  g_xsl[(size_t)BLROWS * DINNER];
__device__ float g_sres[(size_t)BLROWS * DINNER];   // silu(res)
__device__ float g_u  [(size_t)BLROWS * DINNER];    // silu(conv)
__device__ float g_dbc[(size_t)BLROWS * 96];
__device__ bf16  g_dth[(size_t)BLROWS * DTRANK];    // dt_raw split
__device__ bf16  g_dtl[(size_t)BLROWS * DTRANK];
__device__ float g_delta[(size_t)BLROWS * DINNER];
__device__ bf16  g_yh [(size_t)BLROWS * DINNER];    // gated y split
__device__ bf16  g_yl [(size_t)BLROWS * DINNER];
// Pre-split transposed weights ([N,K] K-major)
__device__ bf16  g_WinTh [(size_t)4096 * 1024],  g_WinTl [(size_t)4096 * 1024];
__device__ bf16  g_convTh[(size_t)4 * 2048 * 1024], g_convTl[(size_t)4 * 2048 * 1024];
__device__ bf16  g_WoutTh[(size_t)1024 * 2048], g_WoutTl[(size_t)1024 * 2048];
__device__ bf16  g_WdtTh [(size_t)2048 * 64],   g_WdtTl [(size_t)2048 * 64];

// ---------------------------------------------------------------------------
// PTX helpers
// ---------------------------------------------------------------------------
__device__ __forceinline__ uint32_t smem_u32(const void* p) {
    uint32_t a;
    asm("{ .reg .u64 t; cvta.to.shared.u64 t, %1; cvt.u32.u64 %0, t; }"
        : "=r"(a) : "l"(p));
    return a;
}
__device__ __forceinline__ void ldsm4(uint32_t* r, uint32_t addr) {
    asm volatile("ldmatrix.sync.aligned.m8n8.x4.shared.b16 {%0,%1,%2,%3}, [%4];"
        : "=r"(r[0]), "=r"(r[1]), "=r"(r[2]), "=r"(r[3]) : "r"(addr));
}
__device__ __forceinline__ void mma16816(
    float& d0, float& d1, float& d2, float& d3,
    uint32_t a0, uint32_t a1, uint32_t a2, uint32_t a3,
    uint32_t b0, uint32_t b1)
{
    asm volatile(
        "mma.sync.aligned.m16n8k16.row.col.f32.bf16.bf16.f32 "
        "{%0,%1,%2,%3}, {%4,%5,%6,%7}, {%8,%9}, {%0,%1,%2,%3};"
        : "+f"(d0), "+f"(d1), "+f"(d2), "+f"(d3)
        : "r"(a0), "r"(a1), "r"(a2), "r"(a3), "r"(b0), "r"(b1));
}
__device__ __forceinline__ void cp16(uint32_t dst, const void* src, int nbytes) {
    size_t g = __cvta_generic_to_global(src);
    asm volatile("cp.async.cg.shared.global [%0], [%1], 16, %2;"
                 :: "r"(dst), "l"(g), "r"(nbytes) : "memory");
}
#define CP_COMMIT() asm volatile("cp.async.commit_group;" ::: "memory")
#define CP_WAIT1()  asm volatile("cp.async.wait_group 1;" ::: "memory")
#define CP_WAIT0()  asm volatile("cp.async.wait_group 0;" ::: "memory")

// bf16 2-way split of two floats -> packed bf16x2 (hi, lo)
__device__ __forceinline__ void split2(float x, float y, uint32_t& hi, uint32_t& lo) {
    bf16 hx = __float2bfloat16_rn(x);
    bf16 hy = __float2bfloat16_rn(y);
    __nv_bfloat162 h; h.x = hx; h.y = hy;
    __nv_bfloat162 l = __floats2bfloat162_rn(x - __bfloat162float(hx),
                                             y - __bfloat162float(hy));
    hi = *reinterpret_cast<uint32_t*>(&h);
    lo = *reinterpret_cast<uint32_t*>(&l);
}
// SMEM tile: 128 rows x 32 bf16 (64B/row, 4x16B chunks), xor-swizzled
__device__ __forceinline__ uint32_t swz(int row, int chunk) {
    return (uint32_t)((row << 6) + (((chunk ^ ((row >> 1) & 3)) & 3) << 4));
}
__device__ __forceinline__ float silu(float v) { return v / (1.f + __expf(-v)); }

// ---------------------------------------------------------------------------
// bf16x3 mma GEMM, pre-split operands, cp.async 3-stage pipeline.
// C-tile[128,128] = A[M,K] @ Bt[N,K]^T, fp32 accumulate.
// NTAPS=4: grouped causal conv (row shift per tap, group col base).
// EPI: 0 store fp32; 1 softplus+clip(+bias); 2 bias+silu; 3 GEMM1 (xs->bf16
//      hi/lo when n0<2048, silu(res)->C fp32 otherwise).
// ---------------------------------------------------------------------------
template <int NTAPS, int EPI>
__global__ __launch_bounds__(256) void mma_gemm2(
    const bf16* __restrict__ Ah, const bf16* __restrict__ Al, int lda,
    const bf16* __restrict__ Bh, const bf16* __restrict__ Bl,
    long tap_stride, int ldb,
    float* __restrict__ C, int ldc, int K, const float* __restrict__ bias,
    bf16* __restrict__ xsh, bf16* __restrict__ xsl)
{
    extern __shared__ char dyn[];
    const uint32_t rawb = smem_u32(dyn);
    const uint32_t base = (rawb + 1023u) & ~1023u;

    const int tid  = threadIdx.x;
    const int lane = tid & 31;
    const int wid  = tid >> 5;
    const int wm   = wid & 1;
    const int wn   = wid >> 1;
    const int m0   = blockIdx.y * 128;
    const int n0   = blockIdx.x * 128;
    const int colbase = (NTAPS == 4 && n0 >= 1024) ? 1024 : 0;
    const int NKB = K >> 5;
    const int TOT = NTAPS * NKB;

    const int a_r  = lane & 15;
    const int a_cx = lane >> 4;
    const int b_r  = (lane & 7) + ((lane >> 4) << 3);
    const int b_cx = (lane >> 3) & 1;

    float acc[4][4][4];
#pragma unroll
    for (int i = 0; i < 4; i++)
#pragma unroll
        for (int j = 0; j < 4; j++)
#pragma unroll
            for (int k = 0; k < 4; k++) acc[i][j][k] = 0.f;

    auto issue = [&](int it) {
        int s = it % 3;
        uint32_t sb = base + s * 32768u;
        int tap = (NTAPS == 1) ? 0 : (it / NKB);
        int kb  = it - tap * NKB;
        const bf16* Bhw = Bh + (long)tap * tap_stride;
        const bf16* Blw = Bl + (long)tap * tap_stride;
#pragma unroll
        for (int i = 0; i < 2; i++) {
            int c   = tid + i * 256;      // 0..511
            int row = c >> 2, seg = c & 3;
            uint32_t soff = swz(row, seg);
            // A (hi, lo)
            long arow;
            int nb = 16;
            if (NTAPS == 4) {
                int t = m0 + row;
                bool ok = (t & (LSEQ - 1)) >= (3 - tap);
                arow = ok ? (long)(t + tap - 3) : 0;
                nb = ok ? 16 : 0;
            } else {
                arow = m0 + row;
            }
            const bf16* sa = Ah + arow * lda + colbase + kb * 32 + seg * 8;
            const bf16* sl = Al + arow * lda + colbase + kb * 32 + seg * 8;
            cp16(sb + soff,          sa, nb);
            cp16(sb + 8192 + soff,   sl, nb);
            // B (hi, lo)
            const bf16* sbh = Bhw + (long)(n0 + row) * ldb + kb * 32 + seg * 8;
            const bf16* sbl = Blw + (long)(n0 + row) * ldb + kb * 32 + seg * 8;
            cp16(sb + 16384 + soff,  sbh, 16);
            cp16(sb + 24576 + soff,  sbl, 16);
        }
        CP_COMMIT();
    };

    auto mma_block = [&](int s) {
        uint32_t sb = base + (uint32_t)s * 32768u;
        uint32_t aHiB = sb, aLoB = sb + 8192, bHiB = sb + 16384, bLoB = sb + 24576;
#pragma unroll
        for (int ks = 0; ks < 2; ks++) {
            uint32_t a[4][4], bh[4][2], bx[4][2];
#pragma unroll
            for (int mf = 0; mf < 4; mf++) {
                int row = wm * 64 + mf * 16 + a_r;
                ldsm4(a[mf], aHiB + swz(row, ks * 2 + a_cx));
            }
#pragma unroll
            for (int p = 0; p < 2; p++) {
                int row = wn * 32 + p * 16 + b_r;
                uint32_t t[4];
                ldsm4(t, bHiB + swz(row, ks * 2 + b_cx));
                bh[p * 2][0] = t[0]; bh[p * 2][1] = t[1];
                bh[p * 2 + 1][0] = t[2]; bh[p * 2 + 1][1] = t[3];
            }
#pragma unroll
            for (int mf = 0; mf < 4; mf++)
#pragma unroll
                for (int nf = 0; nf < 4; nf++)
                    mma16816(acc[mf][nf][0], acc[mf][nf][1], acc[mf][nf][2], acc[mf][nf][3],
                             a[mf][0], a[mf][1], a[mf][2], a[mf][3], bh[nf][0], bh[nf][1]);
#pragma unroll
            for (int p = 0; p < 2; p++) {
                int row = wn * 32 + p * 16 + b_r;
                uint32_t t[4];
                ldsm4(t, bLoB + swz(row, ks * 2 + b_cx));
                bx[p * 2][0] = t[0]; bx[p * 2][1] = t[1];
                bx[p * 2 + 1][0] = t[2]; bx[p * 2 + 1][1] = t[3];
            }
#pragma unroll
            for (int mf = 0; mf < 4; mf++)
#pragma unroll
                for (int nf = 0; nf < 4; nf++)
                    mma16816(acc[mf][nf][0], acc[mf][nf][1], acc[mf][nf][2], acc[mf][nf][3],
                             a[mf][0], a[mf][1], a[mf][2], a[mf][3], bx[nf][0], bx[nf][1]);
#pragma unroll
            for (int mf = 0; mf < 4; mf++) {
                int row = wm * 64 + mf * 16 + a_r;
                ldsm4(a[mf], aLoB + swz(row, ks * 2 + a_cx));
            }
#pragma unroll
            for (int mf = 0; mf < 4; mf++)
#pragma unroll
                for (int nf = 0; nf < 4; nf++)
                    mma16816(acc[mf][nf][0], acc[mf][nf][1], acc[mf][nf][2], acc[mf][nf][3],
                             a[mf][0], a[mf][1], a[mf][2], a[mf][3], bh[nf][0], bh[nf][1]);
        }
    };

    issue(0);
    if (TOT > 1) issue(1);
    for (int it = 0; it < TOT; it++) {
        if (it + 2 <= TOT) CP_WAIT1(); else CP_WAIT0();
        __syncthreads();
        mma_block(it % 3);
        if (it + 2 < TOT) issue(it + 2);
    }

    // Epilogue
#pragma unroll
    for (int mf = 0; mf < 4; mf++) {
        int r = m0 + wm * 64 + mf * 16 + (lane >> 2);
#pragma unroll
        for (int nf = 0; nf < 4; nf++) {
            int c = n0 + wn * 32 + nf * 8 + (lane & 3) * 2;
            float v0 = acc[mf][nf][0], v1 = acc[mf][nf][1];
            float v2 = acc[mf][nf][2], v3 = acc[mf][nf][3];
            if (EPI == 1) {
                float b0 = bias[c], b1 = bias[c + 1];
                float x0 = v0 + b0, x1 = v1 + b1, x2 = v2 + b0, x3 = v3 + b1;
                v0 = fminf(fmaxf(fmaxf(x0, 0.f) + log1pf(__expf(-fabsf(x0))), 1e-3f), 0.1f);
                v1 = fminf(fmaxf(fmaxf(x1, 0.f) + log1pf(__expf(-fabsf(x1))), 1e-3f), 0.1f);
                v2 = fminf(fmaxf(fmaxf(x2, 0.f) + log1pf(__expf(-fabsf(x2))), 1e-3f), 0.1f);
                v3 = fminf(fmaxf(fmaxf(x3, 0.f) + log1pf(__expf(-fabsf(x3))), 1e-3f), 0.1f);
            } else if (EPI == 2) {
                float b0 = bias[c], b1 = bias[c + 1];
                v0 = silu(v0 + b0); v1 = silu(v1 + b1);
                v2 = silu(v2 + b0); v3 = silu(v3 + b1);
            }
            if (EPI == 3) {
                if (n0 < 2048) {   // xs half -> bf16 hi/lo
                    uint32_t h, l;
                    split2(v0, v1, h, l);
                    *(uint32_t*)(xsh + (size_t)r * 2048 + c) = h;
                    *(uint32_t*)(xsl + (size_t)r * 2048 + c) = l;
                    split2(v2, v3, h, l);
                    *(uint32_t*)(xsh + (size_t)(r + 8) * 2048 + c) = h;
                    *(uint32_t*)(xsl + (size_t)(r + 8) * 2048 + c) = l;
                } else {           // res half -> silu -> fp32
                    int cc = c - 2048;
                    *(float2*)(C + (size_t)r * ldc + cc)
                        = make_float2(silu(v0), silu(v1));
                    *(float2*)(C + (size_t)(r + 8) * ldc + cc)
                        = make_float2(silu(v2), silu(v3));
                }
            } else {
                *(float2*)(C + (size_t)r * ldc + c)       = make_float2(v0, v1);
                *(float2*)(C + (size_t)(r + 8) * ldc + c) = make_float2(v2, v3);
            }
        }
    }
}

// ---------------------------------------------------------------------------
// Transpose + split: src [R,C] fp32 -> dst_hi/lo [C,R] bf16
// ---------------------------------------------------------------------------
__global__ __launch_bounds__(256) void transpose_split(
    const float* __restrict__ src, bf16* __restrict__ dh, bf16* __restrict__ dl,
    int R, int C)
{
    __shared__ float t[32][33];
    int x = blockIdx.x * 32 + threadIdx.x;
#pragma unroll
    for (int j = 0; j < 4; j++) {
        int y = blockIdx.y * 32 + threadIdx.y + j * 8;
        t[threadIdx.y + j * 8][threadIdx.x] = src[(size_t)y * C + x];
    }
    __syncthreads();
    int x2 = blockIdx.y * 32 + threadIdx.x;
#pragma unroll
    for (int j = 0; j < 4; j++) {
        int y2 = blockIdx.x * 32 + threadIdx.y + j * 8;
        float v = t[threadIdx.x][threadIdx.y + j * 8];
        bf16 h = __float2bfloat16_rn(v);
        dh[(size_t)y2 * R + x2] = h;
        dl[(size_t)y2 * R + x2] = __float2bfloat16_rn(v - __bfloat162float(h));
    }
}

// ---------------------------------------------------------------------------
// Elementwise split: fp32[n] -> bf16 hi/lo
// ---------------------------------------------------------------------------
__global__ __launch_bounds__(256) void split_kernel(
    const float* __restrict__ src, bf16* __restrict__ dh, bf16* __restrict__ dl)
{
    size_t i = ((size_t)blockIdx.x * blockDim.x + threadIdx.x) * 4;
    float4 v = *(const float4*)(src + i);
    uint32_t h0, l0, h1, l1;
    split2(v.x, v.y, h0, l0);
    split2(v.z, v.w, h1, l1);
    *(uint2*)(dh + i) = make_uint2(h0, h1);
    *(uint2*)(dl + i) = make_uint2(l0, l1);
}

// Strided split: dt_raw = dbc[:, :64] -> dth/dtl [4096,64]
__global__ __launch_bounds__(256) void split_dt_kernel(
    const float* __restrict__ dbc, bf16* __restrict__ dh, bf16* __restrict__ dl)
{
    int i = blockIdx.x * blockDim.x + threadIdx.x;   // 0 .. 4096*32-1 (pairs)
    int row = i >> 5;
    int col = (i & 31) * 2;
    float v0 = dbc[(size_t)row * 96 + col];
    float v1 = dbc[(size_t)row * 96 + col + 1];
    uint32_t h, l;
    split2(v0, v1, h, l);
    *(uint32_t*)(dh + (size_t)row * 64 + col) = h;
    *(uint32_t*)(dl + (size_t)row * 64 + col) = l;
}

// ---------------------------------------------------------------------------
// Narrow GEMM: DBC[4096,96] = U @ W_x (fp32 SIMT)
// ---------------------------------------------------------------------------
__global__ __launch_bounds__(256) void gemm_n96_kernel(
    const float* __restrict__ A, const float* __restrict__ B, float* __restrict__ C)
{
    const int BK = 32, NN = 96;
    __shared__ float As[BK][32];
    __shared__ float Bs[BK][NN];

    const int m0 = blockIdx.x * 32;
    const int tid = threadIdx.x;
    const int tx = tid & 15;
    const int ty = tid >> 4;

    float acc[2][6];
#pragma unroll
    for (int r = 0; r < 2; r++)
#pragma unroll
        for (int j = 0; j < 6; j++) acc[r][j] = 0.f;

    for (int k0 = 0; k0 < DINNER; k0 += BK) {
        {
            int row = tid >> 3;
            int cv  = (tid & 7) * 4;
            float4 a = *(const float4*)(A + (size_t)(m0 + row) * DINNER + k0 + cv);
            As[cv + 0][row] = a.x; As[cv + 1][row] = a.y;
            As[cv + 2][row] = a.z; As[cv + 3][row] = a.w;
        }
#pragma unroll
        for (int i = 0; i < 3; i++) {
            int idx  = tid + i * 256;
            int rowB = idx / 24;
            int cv   = (idx % 24) * 4;
            *(float4*)(&Bs[rowB][cv]) =
                *(const float4*)(B + (size_t)(k0 + rowB) * NN + cv);
        }
        __syncthreads();
#pragma unroll
        for (int k = 0; k < BK; k++) {
            float a0 = As[k][ty * 2];
            float a1 = As[k][ty * 2 + 1];
#pragma unroll
            for (int j = 0; j < 6; j++) {
                float bb = Bs[k][tx * 6 + j];
                acc[0][j] = fmaf(a0, bb, acc[0][j]);
                acc[1][j] = fmaf(a1, bb, acc[1][j]);
            }
        }
        __syncthreads();
    }
#pragma unroll
    for (int r = 0; r < 2; r++) {
        int m = m0 + ty * 2 + r;
#pragma unroll
        for (int j = 0; j < 6; j++)
            C[(size_t)m * 96 + tx * 6 + j] = acc[r][j];
    }
}

// ---------------------------------------------------------------------------
// Selective scan, fused gate; writes gated y as bf16 hi/lo
// ---------------------------------------------------------------------------
__global__ __launch_bounds__(256) void scan_kernel(
    const float* __restrict__ delta, const float* __restrict__ u,
    const float* __restrict__ dbc, const float* __restrict__ A_log,
    const float* __restrict__ Dp, const float* __restrict__ sres,
    bf16* __restrict__ Yh, bf16* __restrict__ Yl)
{
    int tid = blockIdx.x * blockDim.x + threadIdx.x;
    int n = tid & 15;
    int d = (tid >> 4) & (DINNER - 1);
    int b = tid >> 15;

    const float a  = -__expf(A_log[d * DSTATE + n]);
    const float Dd = Dp[d];

    const size_t rowbase = (size_t)b * LSEQ;
    const float* dptr = delta + rowbase * DINNER + d;
    const float* uptr = u     + rowbase * DINNER + d;
    const float* bc   = dbc   + rowbase * 96;
    const float* rp   = sres  + rowbase * DINNER + d;
    bf16* yh = Yh + rowbase * DINNER + d;
    bf16* yl = Yl + rowbase * DINNER + d;

    float h = 0.f;
    for (int t = 0; t < LSEQ; t++) {
        float de = dptr[(size_t)t * DINNER];
        float uu = uptr[(size_t)t * DINNER];
        float Bn = bc[t * 96 + DTRANK + n];
        float Cn = bc[t * 96 + DTRANK + DSTATE + n];
        float dA = __expf(de * a);
        h = fmaf(dA, h, de * uu * Bn);
        float p = h * Cn;
        p += __shfl_xor_sync(0xffffffffu, p, 8);
        p += __shfl_xor_sync(0xffffffffu, p, 4);
        p += __shfl_xor_sync(0xffffffffu, p, 2);
        p += __shfl_xor_sync(0xffffffffu, p, 1);
        if (n == 0) {
            float yv = fmaf(uu, Dd, p) * rp[(size_t)t * DINNER];
            bf16 hh = __float2bfloat16_rn(yv);
            yh[(size_t)t * DINNER] = hh;
            yl[(size_t)t * DINNER] = __float2bfloat16_rn(yv - __bfloat162float(hh));
        }
    }
}

// ---------------------------------------------------------------------------
// Launch
// ---------------------------------------------------------------------------
static const int GEMM_SMEM = 3 * 32768 + 1024;

extern "C" void kernel_launch(void* const* d_in, const int* in_sizes, int n_in,
                              void* d_out, int out_size)
{
    (void)in_sizes; (void)n_in; (void)out_size;
    const float* x      = (const float*)d_in[0];
    const float* W_in   = (const float*)d_in[1];
    const float* conv_k = (const float*)d_in[2];
    const float* conv_b = (const float*)d_in[3];
    const float* W_x    = (const float*)d_in[4];
    const float* W_dt   = (const float*)d_in[5];
    const float* b_dt   = (const float*)d_in[6];
    const float* A_log  = (const float*)d_in[7];
    const float* Dvec   = (const float*)d_in[8];
    const float* W_out  = (const float*)d_in[9];
    float* out = (float*)d_out;

    bf16 *xh, *xl, *xsh, *xsl, *dth, *dtl, *yh, *yl;
    bf16 *winTh, *winTl, *convTh, *convTl, *woutTh, *woutTl, *wdtTh, *wdtTl;
    float *sres, *u, *dbc, *delta;
    cudaGetSymbolAddress((void**)&xh,   g_xh);   cudaGetSymbolAddress((void**)&xl,   g_xl);
    cudaGetSymbolAddress((void**)&xsh,  g_xsh);  cudaGetSymbolAddress((void**)&xsl,  g_xsl);
    cudaGetSymbolAddress((void**)&sres, g_sres); cudaGetSymbolAddress((void**)&u,    g_u);
    cudaGetSymbolAddress((void**)&dbc,  g_dbc);
    cudaGetSymbolAddress((void**)&dth,  g_dth);  cudaGetSymbolAddress((void**)&dtl,  g_dtl);
    cudaGetSymbolAddress((void**)&delta,g_delta);
    cudaGetSymbolAddress((void**)&yh,   g_yh);   cudaGetSymbolAddress((void**)&yl,   g_yl);
    cudaGetSymbolAddress((void**)&winTh, g_WinTh);  cudaGetSymbolAddress((void**)&winTl, g_WinTl);
    cudaGetSymbolAddress((void**)&convTh,g_convTh); cudaGetSymbolAddress((void**)&convTl,g_convTl);
    cudaGetSymbolAddress((void**)&woutTh,g_WoutTh); cudaGetSymbolAddress((void**)&woutTl,g_WoutTl);
    cudaGetSymbolAddress((void**)&wdtTh, g_WdtTh);  cudaGetSymbolAddress((void**)&wdtTl, g_WdtTl);

    cudaFuncSetAttribute(mma_gemm2<1, 3>, cudaFuncAttributeMaxDynamicSharedMemorySize, GEMM_SMEM);
    cudaFuncSetAttribute(mma_gemm2<4, 2>, cudaFuncAttributeMaxDynamicSharedMemorySize, GEMM_SMEM);
    cudaFuncSetAttribute(mma_gemm2<1, 1>, cudaFuncAttributeMaxDynamicSharedMemorySize, GEMM_SMEM);
    cudaFuncSetAttribute(mma_gemm2<1, 0>, cudaFuncAttributeMaxDynamicSharedMemorySize, GEMM_SMEM);

    // 0) weight transpose+split, activation split
    transpose_split<<<dim3(4096 / 32, 1024 / 32), dim3(32, 8)>>>(W_in, winTh, winTl, 1024, 4096);
    for (int w = 0; w < 4; w++)
        transpose_split<<<dim3(2048 / 32, 1024 / 32), dim3(32, 8)>>>(
            conv_k + (size_t)w * 1024 * 2048,
            convTh + (size_t)w * 2048 * 1024, convTl + (size_t)w * 2048 * 1024, 1024, 2048);
    transpose_split<<<dim3(1024 / 32, 2048 / 32), dim3(32, 8)>>>(W_out, woutTh, woutTl, 2048, 1024);
    transpose_split<<<dim3(2048 / 32, 64 / 32), dim3(32, 8)>>>(W_dt, wdtTh, wdtTl, 64, 2048);
    split_kernel<<<(BLROWS * DMODEL / 4) / 256, 256>>>(x, xh, xl);

    // 1) GEMM1: xs -> bf16 hi/lo, silu(res) -> sres fp32
    mma_gemm2<1, 3><<<dim3(32, 32), 256, GEMM_SMEM>>>(
        xh, xl, DMODEL, winTh, winTl, 0, DMODEL, sres, DINNER, DMODEL, nullptr, xsh, xsl);

    // 2) grouped causal conv (4 taps fused) + bias + silu -> u fp32
    mma_gemm2<4, 2><<<dim3(16, 32), 256, GEMM_SMEM>>>(
        xsh, xsl, DINNER, convTh, convTl, (long)2048 * 1024, 1024,
        u, DINNER, 1024, conv_b, nullptr, nullptr);

    // 3) dbc = u @ W_x (fp32 SIMT)
    gemm_n96_kernel<<<128, 256>>>(u, W_x, dbc);

    // 4) split dt_raw, delta GEMM (K=64) + softplus + clip
    split_dt_kernel<<<(BLROWS * 32) / 256, 256>>>(dbc, dth, dtl);
    mma_gemm2<1, 1><<<dim3(16, 32), 256, GEMM_SMEM>>>(
        dth, dtl, DTRANK, wdtTh, wdtTl, 0, DTRANK,
        delta, DINNER, DTRANK, b_dt, nullptr, nullptr);

    // 5) selective scan + fused gate -> yh/yl bf16
    scan_kernel<<<256, 256>>>(delta, u, dbc, A_log, Dvec, sres, yh, yl);

    // 6) out = y @ W_out
    mma_gemm2<1, 0><<<dim3(8, 32), 256, GEMM_SMEM>>>(
        yh, yl, DINNER, woutTh, woutTl, 0, DINNER,
        out, DMODEL, DINNER, nullptr, nullptr, nullptr);
}